// round 7
// baseline (speedup 1.0000x reference)
#include <cuda_runtime.h>

// Problem constants (static per reference)
#define NEV   250000
#define CB    9
#define HV    180
#define WV    240
#define BB    8
#define PLANE (HV*WV)              // 43200
#define NVOX  (2*CB*PLANE*BB)      // 6,220,800
#define TABN  1025                 // table entries over s in [-1,1], h = 2/1024
#define OUTSZ 640
#define NIMG  (BB * 2 * CB)        // 144 output images

#define BINCELLS 64.0f             // (1/8) / (2/1024)
#define TSCALE   512.0f            // (tn+1) * (1024/2)

// k_front block-range dispatch (segmax/table first so they overlap vox-zero)
#define NB_SEG 256
#define KCH 5
#define NB_TAB_X 5                 // 5 x 256 threads = 1280 >= 1025
#define NB_TAB (NB_TAB_X * (100 / KCH))   // 100
#define NF4   (NVOX / 4)           // 1,555,200 float4s
#define NB_VOX ((NF4 + 1023) / 1024)      // 1519 blocks, 1024 f4 per block
#define NB_FRONT (NB_SEG + NB_TAB + NB_VOX)

__device__ float        g_vox[NVOX];
__device__ float        g_tab[TABN];    // zero at process start; re-zeroed by k_resize tail
__device__ unsigned int g_bmax[BB];     // ditto

// ---------------------------------------------------------------------------
// k_front: fused {segmax | table | vox-zero} via disjoint block ranges.
// g_tab/g_bmax are already zero on entry (launch invariant, see k_resize tail).
// ---------------------------------------------------------------------------
__global__ void __launch_bounds__(256) k_front(
    const float* __restrict__ ev,
    const float* __restrict__ W1, const float* __restrict__ b1,
    const float* __restrict__ W2, const float* __restrict__ b2,
    const float* __restrict__ W3, const float* __restrict__ b3)
{
    int bid = blockIdx.x;

    if (bid < NB_SEG) {
        // ---- segmax: per-batch max of t (positive floats: uint order) ----
        __shared__ unsigned int sm[BB];
        if (threadIdx.x < BB) sm[threadIdx.x] = 0u;
        __syncthreads();
        for (int e = bid * 256 + threadIdx.x; e < NEV; e += NB_SEG * 256) {
            float t = __ldg(&ev[5 * e + 2]);
            int   b = (int)__ldg(&ev[5 * e + 4]);
            atomicMax(&sm[b], __float_as_uint(t));
        }
        __syncthreads();
        if (threadIdx.x < BB) atomicMax(&g_bmax[threadIdx.x], sm[threadIdx.x]);
        return;
    }

    if (bid < NB_SEG + NB_TAB) {
        // ---- table: f(s) on 1025-pt grid, KCH=5 neuron chunks ----
        int tb = bid - NB_SEG;
        int bx = tb % NB_TAB_X;
        int k0 = (tb / NB_TAB_X) * KCH;
        __shared__ float sW2[100 * KCH];
        __shared__ float sW1[100], sb1[100];
        for (int i = threadIdx.x; i < 100 * KCH; i += 256)
            sW2[i] = W2[(i / KCH) * 100 + k0 + (i % KCH)];
        if (threadIdx.x < 100) {
            sW1[threadIdx.x] = W1[threadIdx.x];
            sb1[threadIdx.x] = b1[threadIdx.x];
        }
        __syncthreads();
        int e = bx * 256 + threadIdx.x;
        if (e >= TABN) return;
        float s = (float)e * (2.0f / 1024.0f) - 1.0f;
        float acc[KCH];
#pragma unroll
        for (int k = 0; k < KCH; k++) acc[k] = 0.f;
#pragma unroll 5
        for (int j = 0; j < 100; j++) {
            float pre = fmaf(sW1[j], s, sb1[j]);
            float hj  = fmaxf(pre, 0.1f * pre);   // LeakyReLU(0.1)
#pragma unroll
            for (int k = 0; k < KCH; k++)
                acc[k] = fmaf(hj, sW2[j * KCH + k], acc[k]);
        }
        float f = (k0 == 0) ? __ldg(&b3[0]) : 0.f;
#pragma unroll
        for (int k = 0; k < KCH; k++) {
            float pre = acc[k] + __ldg(&b2[k0 + k]);
            float h2  = fmaxf(pre, 0.1f * pre);
            f = fmaf(h2, __ldg(&W3[k0 + k]), f);
        }
        atomicAdd(&g_tab[e], f);
        return;
    }

    // ---- vox zero: 4 interleaved float4 stores per thread ----
    int vb = bid - NB_SEG - NB_TAB;
    int base = vb * 1024 + threadIdx.x;
    float4 z = make_float4(0.f, 0.f, 0.f, 0.f);
#pragma unroll
    for (int k = 0; k < 4; k++) {
        int j = base + k * 256;
        if (j < NF4) ((float4*)g_vox)[j] = z;
    }
}

// ---------------------------------------------------------------------------
// scatter: 4 events per thread via 5 aligned float4 loads (events 4k..4k+3 =
// 20 floats at byte offset 80k, 16B-aligned). RED-lane count invariant
// (~2.25M spread f32 lanes ~ 11-12us floor); this trims load/issue overhead.
// ---------------------------------------------------------------------------
__global__ void __launch_bounds__(256) k_scatter(const float* __restrict__ ev) {
    int tid = blockIdx.x * blockDim.x + threadIdx.x;
    if (tid >= NEV / 4) return;
    const float4* p4 = (const float4*)(ev + 20 * (size_t)tid);
    float4 v0 = __ldg(p4 + 0), v1 = __ldg(p4 + 1), v2 = __ldg(p4 + 2);
    float4 v3 = __ldg(p4 + 3), v4 = __ldg(p4 + 4);
    float f[20] = {v0.x, v0.y, v0.z, v0.w, v1.x, v1.y, v1.z, v1.w,
                   v2.x, v2.y, v2.z, v2.w, v3.x, v3.y, v3.z, v3.w,
                   v4.x, v4.y, v4.z, v4.w};
#pragma unroll
    for (int j = 0; j < 4; j++) {
        float x = f[5 * j + 0], y = f[5 * j + 1], t = f[5 * j + 2];
        float p = f[5 * j + 3], bf = f[5 * j + 4];
        int b = (int)bf;
        float tn = t / __uint_as_float(g_bmax[b]);  // matches jnp fp32 divide
        int vbase = (int)x + WV * (int)y + (CB * PLANE) * (int)p
                  + (2 * CB * PLANE) * b;
        float u0 = (tn + 1.0f) * TSCALE;
#pragma unroll
        for (int i = 0; i < CB; i++) {
            float u = u0 - BINCELLS * (float)i;     // exact fp32 arithmetic
            int i0 = (int)u;
            if (i0 > TABN - 2) i0 = TABN - 2;       // tn == 1.0 edge
            float fr = u - (float)i0;
            float t0 = g_tab[i0], t1 = g_tab[i0 + 1];
            float val = tn * fmaf(fr, t1 - t0, t0);
            atomicAdd(&g_vox[vbase + i * PLANE], val);
        }
    }
}

// ---------------------------------------------------------------------------
// resize: letterbox bilinear (180,240)->(480,640), pad rows 114 inline.
// Block 0 re-zeroes g_tab/g_bmax for the NEXT launch (scatter done; nothing
// here reads them) -- maintains the launch invariant. Near HBM store floor.
// ---------------------------------------------------------------------------
__global__ void k_resize(float* __restrict__ out) {
    if (blockIdx.x == 0) {
        for (int i = threadIdx.x; i < TABN; i += blockDim.x) g_tab[i] = 0.f;
        if (threadIdx.x < BB) g_bmax[threadIdx.x] = 0u;
    }
    int gid = blockIdx.x * blockDim.x + threadIdx.x;   // 144*640*80
    if (gid >= NIMG * OUTSZ * (OUTSZ / 8)) return;
    int m  = gid % (OUTSZ / 8);
    int r  = gid / (OUTSZ / 8);
    int oy = r % OUTSZ;
    int bc = r / OUTSZ;                                // b*18 + c
    float4* o = (float4*)(out + (((size_t)bc * OUTSZ + oy) * OUTSZ + m * 8));
    if (oy < 80 || oy >= 560) {
        float4 v = make_float4(114.f, 114.f, 114.f, 114.f);
        __stcs(o, v);
        __stcs(o + 1, v);
        return;
    }
    int c = bc % (2 * CB), b = bc / (2 * CB);
    int pp = c / CB, bin = c % CB;
    const float* vb = g_vox + (size_t)PLANE * (bin + CB * (pp + 2 * b));

    int oyr = oy - 80;
    float fy  = 0.375f * (float)oyr - 0.3125f;
    float fyf = floorf(fy);
    int   y0  = (int)fyf;
    float wy  = fy - fyf;
    int y0c = y0 < 0 ? 0 : y0;
    int y1c = (y0 + 1 > HV - 1) ? (HV - 1) : (y0 + 1);
    const float* r0 = vb + y0c * WV;
    const float* r1 = vb + y1c * WV;

    int xb = 3 * m - 1;
    float a0[5], a1[5];
#pragma unroll
    for (int i = 0; i < 5; i++) {
        int xc = xb + i;
        xc = xc < 0 ? 0 : (xc > WV - 1 ? WV - 1 : xc);
        a0[i] = __ldg(&r0[xc]);
        a1[i] = __ldg(&r1[xc]);
    }
    const float wx[8] = {0.6875f, 0.0625f, 0.4375f, 0.8125f,
                         0.1875f, 0.5625f, 0.9375f, 0.3125f};
    const int   ix[8] = {0, 1, 1, 1, 2, 2, 2, 3};
    float o8[8];
#pragma unroll
    for (int k = 0; k < 8; k++) {
        int i = ix[k];
        float h0 = fmaf(wx[k], a0[i + 1] - a0[i], a0[i]);
        float h1 = fmaf(wx[k], a1[i + 1] - a1[i], a1[i]);
        o8[k] = fmaf(wy, h1 - h0, h0);
    }
    __stcs(o,     make_float4(o8[0], o8[1], o8[2], o8[3]));
    __stcs(o + 1, make_float4(o8[4], o8[5], o8[6], o8[7]));
}

// ---------------------------------------------------------------------------
// launch: strictly serial, 3 kernels (multi-stream overlap was a measured
// regression in R4 — do not reintroduce).
// ---------------------------------------------------------------------------
extern "C" void kernel_launch(void* const* d_in, const int* in_sizes, int n_in,
                              void* d_out, int out_size) {
    const float* ev = (const float*)d_in[0];
    const float* W1 = (const float*)d_in[1];
    const float* b1 = (const float*)d_in[2];
    const float* W2 = (const float*)d_in[3];
    const float* b2 = (const float*)d_in[4];
    const float* W3 = (const float*)d_in[5];
    const float* b3 = (const float*)d_in[6];
    float* out = (float*)d_out;

    k_front<<<NB_FRONT, 256>>>(ev, W1, b1, W2, b2, W3, b3);
    k_scatter<<<(NEV / 4 + 255) / 256, 256>>>(ev);
    k_resize<<<(NIMG * OUTSZ * (OUTSZ / 8) + 255) / 256, 256>>>(out);
}

// round 8
// speedup vs baseline: 1.6542x; 1.6542x over previous
#include <cuda_runtime.h>

// Problem constants (static per reference)
#define NEV   250000
#define CB    9
#define HV    180
#define WV    240
#define BB    8
#define PLANE (HV*WV)              // 43200
#define NVOX  (2*CB*PLANE*BB)      // 6,220,800
#define TABN  1025                 // table entries over s in [-1,1], h = 2/1024
#define OUTSZ 640
#define NIMG  (BB * 2 * CB)        // 144 output images

#define BINCELLS 64.0f             // (1/8) / (2/1024)
#define TSCALE   512.0f            // (tn+1) * (1024/2)

// k_front block-range dispatch (segmax/table first so they overlap vox-zero)
#define NB_SEG 256
#define KCH 5
#define NB_TAB_X 5                 // 5 x 256 threads = 1280 >= 1025
#define NB_TAB (NB_TAB_X * (100 / KCH))   // 100
#define NB_VOX (NVOX / 4 / 256)    // 6075 (exact), 1 float4 per thread (R6 form)
#define NB_FRONT (NB_SEG + NB_TAB + NB_VOX)

// resize block split: pad blocks first (independent), core blocks after
#define NB_PAD  (NIMG * 160 * (OUTSZ / 8) / 256)   // 7200
#define NB_CORE (NIMG * 480 * (OUTSZ / 8) / 256)   // 21600

__device__ float        g_vox[NVOX];
__device__ float        g_tab[TABN];    // zero at process start; re-zeroed by k_resize tail
__device__ unsigned int g_bmax[BB];     // ditto

// ---------------------------------------------------------------------------
// k_front: fused {segmax | table | vox-zero} via disjoint block ranges.
// (R6 form exactly — R7's fatter vox-zero blocks measured slower.)
// ---------------------------------------------------------------------------
__global__ void __launch_bounds__(256) k_front(
    const float* __restrict__ ev,
    const float* __restrict__ W1, const float* __restrict__ b1,
    const float* __restrict__ W2, const float* __restrict__ b2,
    const float* __restrict__ W3, const float* __restrict__ b3)
{
    int bid = blockIdx.x;

    if (bid < NB_SEG) {
        // ---- segmax: per-batch max of t (positive floats: uint order) ----
        __shared__ unsigned int sm[BB];
        if (threadIdx.x < BB) sm[threadIdx.x] = 0u;
        __syncthreads();
        for (int e = bid * 256 + threadIdx.x; e < NEV; e += NB_SEG * 256) {
            float t = __ldg(&ev[5 * e + 2]);
            int   b = (int)__ldg(&ev[5 * e + 4]);
            atomicMax(&sm[b], __float_as_uint(t));
        }
        __syncthreads();
        if (threadIdx.x < BB) atomicMax(&g_bmax[threadIdx.x], sm[threadIdx.x]);
        return;
    }

    if (bid < NB_SEG + NB_TAB) {
        // ---- table: f(s) on 1025-pt grid, KCH=5 neuron chunks ----
        int tb = bid - NB_SEG;
        int bx = tb % NB_TAB_X;
        int k0 = (tb / NB_TAB_X) * KCH;
        __shared__ float sW2[100 * KCH];
        __shared__ float sW1[100], sb1[100];
        for (int i = threadIdx.x; i < 100 * KCH; i += 256)
            sW2[i] = W2[(i / KCH) * 100 + k0 + (i % KCH)];
        if (threadIdx.x < 100) {
            sW1[threadIdx.x] = W1[threadIdx.x];
            sb1[threadIdx.x] = b1[threadIdx.x];
        }
        __syncthreads();
        int e = bx * 256 + threadIdx.x;
        if (e >= TABN) return;
        float s = (float)e * (2.0f / 1024.0f) - 1.0f;
        float acc[KCH];
#pragma unroll
        for (int k = 0; k < KCH; k++) acc[k] = 0.f;
#pragma unroll 5
        for (int j = 0; j < 100; j++) {
            float pre = fmaf(sW1[j], s, sb1[j]);
            float hj  = fmaxf(pre, 0.1f * pre);   // LeakyReLU(0.1)
#pragma unroll
            for (int k = 0; k < KCH; k++)
                acc[k] = fmaf(hj, sW2[j * KCH + k], acc[k]);
        }
        float f = (k0 == 0) ? __ldg(&b3[0]) : 0.f;
#pragma unroll
        for (int k = 0; k < KCH; k++) {
            float pre = acc[k] + __ldg(&b2[k0 + k]);
            float h2  = fmaxf(pre, 0.1f * pre);
            f = fmaf(h2, __ldg(&W3[k0 + k]), f);
        }
        atomicAdd(&g_tab[e], f);
        return;
    }

    // ---- vox zero: 1 float4 store per thread (R6 form) ----
    int i = (bid - NB_SEG - NB_TAB) * 256 + threadIdx.x;
    ((float4*)g_vox)[i] = make_float4(0.f, 0.f, 0.f, 0.f);
}

// ---------------------------------------------------------------------------
// scatter: 1 event/thread (R6 form — R7's 4-events/thread collapsed grid
// parallelism and regressed 2x). Triggers PDL so k_resize's pad blocks can
// launch and overlap; vox-reading blocks gate on grid-dependency sync.
// ---------------------------------------------------------------------------
__global__ void __launch_bounds__(256) k_scatter(const float* __restrict__ ev) {
    cudaTriggerProgrammaticLaunchCompletion();
    int e = blockIdx.x * blockDim.x + threadIdx.x;
    if (e >= NEV) return;
    float x  = __ldg(&ev[5 * e + 0]);
    float y  = __ldg(&ev[5 * e + 1]);
    float t  = __ldg(&ev[5 * e + 2]);
    float p  = __ldg(&ev[5 * e + 3]);
    float bf = __ldg(&ev[5 * e + 4]);
    int b = (int)bf;
    float tn = t / __uint_as_float(g_bmax[b]);      // matches jnp fp32 divide
    int vbase = (int)x + WV * (int)y + (CB * PLANE) * (int)p + (2 * CB * PLANE) * b;
    float u0 = (tn + 1.0f) * TSCALE;                // grid coord of s = tn - 0
#pragma unroll
    for (int i = 0; i < CB; i++) {
        float u = u0 - BINCELLS * (float)i;         // exact fp32 arithmetic
        int i0 = (int)u;
        if (i0 > TABN - 2) i0 = TABN - 2;           // tn == 1.0 edge
        float fr = u - (float)i0;
        float t0 = g_tab[i0], t1 = g_tab[i0 + 1];
        float val = tn * fmaf(fr, t1 - t0, t0);
        atomicAdd(&g_vox[vbase + i * PLANE], val);
    }
}

// ---------------------------------------------------------------------------
// resize (PDL secondary): pad blocks [0, NB_PAD) write the 114-rows with NO
// dependency on scatter -> they run concurrently with it. Core blocks wait on
// cudaGridDependencySynchronize() before reading vox. g_tab/g_bmax re-zero
// sits BEHIND the sync (scatter reads them until it completes).
// ---------------------------------------------------------------------------
__global__ void __launch_bounds__(256) k_resize(float* __restrict__ out) {
    int bid = blockIdx.x;

    if (bid < NB_PAD) {
        // ---- pad: rows [0,80) and [560,640) = 114.0 (independent) ----
        int gid = bid * 256 + threadIdx.x;
        int m  = gid % (OUTSZ / 8);
        int r  = gid / (OUTSZ / 8);
        int pr = r % 160;
        int bc = r / 160;
        int oy = (pr < 80) ? pr : pr + 480;
        float4* o = (float4*)(out + (((size_t)bc * OUTSZ + oy) * OUTSZ + m * 8));
        float4 v = make_float4(114.f, 114.f, 114.f, 114.f);
        __stcs(o, v);
        __stcs(o + 1, v);
        return;
    }

    cudaGridDependencySynchronize();   // wait for scatter's vox to be complete

    if (bid == NB_PAD) {               // safe now: scatter no longer reads tab/bmax
        for (int i = threadIdx.x; i < TABN; i += 256) g_tab[i] = 0.f;
        if (threadIdx.x < BB) g_bmax[threadIdx.x] = 0u;
    }

    int gid = (bid - NB_PAD) * 256 + threadIdx.x;   // over 144*480*80
    int m   = gid % (OUTSZ / 8);
    int r   = gid / (OUTSZ / 8);
    int oyr = r % 480;
    int bc  = r / 480;
    int oy  = oyr + 80;
    float4* o = (float4*)(out + (((size_t)bc * OUTSZ + oy) * OUTSZ + m * 8));

    int c = bc % (2 * CB), b = bc / (2 * CB);
    int pp = c / CB, bin = c % CB;
    const float* vb = g_vox + (size_t)PLANE * (bin + CB * (pp + 2 * b));

    float fy  = 0.375f * (float)oyr - 0.3125f;
    float fyf = floorf(fy);
    int   y0  = (int)fyf;
    float wy  = fy - fyf;
    int y0c = y0 < 0 ? 0 : y0;
    int y1c = (y0 + 1 > HV - 1) ? (HV - 1) : (y0 + 1);
    const float* r0 = vb + y0c * WV;
    const float* r1 = vb + y1c * WV;

    int xb = 3 * m - 1;
    float a0[5], a1[5];
#pragma unroll
    for (int i = 0; i < 5; i++) {
        int xc = xb + i;
        xc = xc < 0 ? 0 : (xc > WV - 1 ? WV - 1 : xc);
        a0[i] = __ldg(&r0[xc]);
        a1[i] = __ldg(&r1[xc]);
    }
    const float wx[8] = {0.6875f, 0.0625f, 0.4375f, 0.8125f,
                         0.1875f, 0.5625f, 0.9375f, 0.3125f};
    const int   ix[8] = {0, 1, 1, 1, 2, 2, 2, 3};
    float o8[8];
#pragma unroll
    for (int k = 0; k < 8; k++) {
        int i = ix[k];
        float h0 = fmaf(wx[k], a0[i + 1] - a0[i], a0[i]);
        float h1 = fmaf(wx[k], a1[i + 1] - a1[i], a1[i]);
        o8[k] = fmaf(wy, h1 - h0, h0);
    }
    __stcs(o,     make_float4(o8[0], o8[1], o8[2], o8[3]));
    __stcs(o + 1, make_float4(o8[4], o8[5], o8[6], o8[7]));
}

// ---------------------------------------------------------------------------
// launch: single stream, 3 sequential nodes; resize uses PDL so its pad
// blocks overlap scatter's tail (NOT multi-stream fork — that regressed).
// ---------------------------------------------------------------------------
extern "C" void kernel_launch(void* const* d_in, const int* in_sizes, int n_in,
                              void* d_out, int out_size) {
    const float* ev = (const float*)d_in[0];
    const float* W1 = (const float*)d_in[1];
    const float* b1 = (const float*)d_in[2];
    const float* W2 = (const float*)d_in[3];
    const float* b2 = (const float*)d_in[4];
    const float* W3 = (const float*)d_in[5];
    const float* b3 = (const float*)d_in[6];
    float* out = (float*)d_out;

    k_front<<<NB_FRONT, 256>>>(ev, W1, b1, W2, b2, W3, b3);
    k_scatter<<<(NEV + 255) / 256, 256>>>(ev);

    cudaLaunchConfig_t cfg = {};
    cfg.gridDim  = dim3(NB_PAD + NB_CORE, 1, 1);
    cfg.blockDim = dim3(256, 1, 1);
    cfg.dynamicSmemBytes = 0;
    cfg.stream = 0;
    cudaLaunchAttribute attr[1];
    attr[0].id = cudaLaunchAttributeProgrammaticStreamSerialization;
    attr[0].val.programmaticStreamSerializationAllowed = 1;
    cfg.attrs = attr;
    cfg.numAttrs = 1;
    cudaLaunchKernelEx(&cfg, k_resize, out);
}